// round 5
// baseline (speedup 1.0000x reference)
#include <cuda_runtime.h>
#include <cuda_bf16.h>
#include <cstdint>

// Problem constants (fixed by dataset)
#define BATCH   131072
#define UNITS   512
#define DIMK    64
#define GRID_X  148
#define NTHREADS 256               // 8 warps; each warp owns a 16-row unit
#define NWARPS_TOTAL (GRID_X * 8)  // 1184
#define NUNITS  (BATCH / 16)       // 8192

// ---------------- SMEM layout ----------------
// bf16 W rows padded to 144B -> ldmatrix conflict-free, 16B aligned.
static constexpr int ROW_BYTES = 144;
static constexpr int SM_WSQ = 0;                          // 512 f32 -> 2048
static constexpr int SM_WST = 2048;                       // 512*144 = 73728
static constexpr int SMEM_TOTAL = SM_WST + 512 * ROW_BYTES;   // 75776

static __device__ __forceinline__ uint32_t smem_u32(const void* p) {
    uint32_t a;
    asm("{ .reg .u64 t; cvta.to.shared.u64 t, %1; cvt.u32.u64 %0, t; }" : "=r"(a) : "l"(p));
    return a;
}

static __device__ __forceinline__ void ldsm_x4(uint32_t& r0, uint32_t& r1, uint32_t& r2,
                                               uint32_t& r3, uint32_t addr) {
    asm volatile("ldmatrix.sync.aligned.m8n8.x4.shared.b16 {%0,%1,%2,%3}, [%4];"
                 : "=r"(r0), "=r"(r1), "=r"(r2), "=r"(r3) : "r"(addr));
}

static __device__ __forceinline__ void mma_bf16(float c[4], uint32_t a0, uint32_t a1,
                                                uint32_t a2, uint32_t a3,
                                                uint32_t b0, uint32_t b1) {
    asm volatile(
        "mma.sync.aligned.m16n8k16.row.col.f32.bf16.bf16.f32 "
        "{%0,%1,%2,%3}, {%4,%5,%6,%7}, {%8,%9}, {%0,%1,%2,%3};"
        : "+f"(c[0]), "+f"(c[1]), "+f"(c[2]), "+f"(c[3])
        : "r"(a0), "r"(a1), "r"(a2), "r"(a3), "r"(b0), "r"(b1));
}

static __device__ __forceinline__ uint32_t pack_bf16(float a, float b) {
    __nv_bfloat162 t = __floats2bfloat162_rn(a, b);
    return *reinterpret_cast<uint32_t*>(&t);
}

__global__ void __launch_bounds__(NTHREADS, 1)
l2dist_kernel(const float* __restrict__ x, const float* __restrict__ w,
              float* __restrict__ out) {
    extern __shared__ char smem[];
    const uint32_t sb = smem_u32(smem);
    const int tid  = threadIdx.x;
    const int wid  = tid >> 5;
    const int lane = tid & 31;

    // ---- Stage W -> bf16 SMEM (padded rows) + exact fp32 ||w||^2, once ----
    #pragma unroll
    for (int rr = 0; rr < 2; rr++) {
        const int u = rr * NTHREADS + tid;
        const float* wr = w + (size_t)u * DIMK;
        float sq = 0.f;
        #pragma unroll
        for (int g = 0; g < 8; g++) {
            float4 a = *reinterpret_cast<const float4*>(wr + 8 * g);
            float4 b = *reinterpret_cast<const float4*>(wr + 8 * g + 4);
            sq += a.x * a.x + a.y * a.y + a.z * a.z + a.w * a.w
                + b.x * b.x + b.y * b.y + b.z * b.z + b.w * b.w;
            uint4 pk;
            pk.x = pack_bf16(a.x, a.y); pk.y = pack_bf16(a.z, a.w);
            pk.z = pack_bf16(b.x, b.y); pk.w = pack_bf16(b.z, b.w);
            *reinterpret_cast<uint4*>(smem + SM_WST + u * ROW_BYTES + g * 16) = pk;
        }
        *reinterpret_cast<float*>(smem + SM_WSQ + u * 4) = sq;
    }
    __syncthreads();   // the ONLY block-wide barrier

    const int gq  = lane >> 2;          // 0..7
    const int qq  = lane & 3;           // 0..3
    const int odd = lane & 1;
    const int cq  = (qq & 2) * 2;       // 0 or 4

    // B ldmatrix base (col-within-16 = lane&15, k-half = lane>>4)
    const uint32_t bb = sb + SM_WST + (uint32_t)(lane & 15) * ROW_BYTES
                      + (uint32_t)((lane >> 4) * 16);

    const int gwarp = blockIdx.x * 8 + wid;

    for (int u = gwarp; u < NUNITS; u += NWARPS_TOTAL) {
        const int row0 = u * 16;

        // ---- Load this warp's 16 x-rows directly from global ----
        // Thread covers rows (row0+gq) and (row0+gq+8), k = {2qq,2qq+1}+{0,8}+16*ks
        const float* xr0 = x + (size_t)(row0 + gq) * DIMK + 2 * qq;
        const float* xr1 = xr0 + (size_t)8 * DIMK;
        float2 xlo[4][2], xhi[4][2];
        #pragma unroll
        for (int ks = 0; ks < 4; ks++) {
            #pragma unroll
            for (int h = 0; h < 2; h++) {
                xlo[ks][h] = __ldcs(reinterpret_cast<const float2*>(xr0 + ks * 16 + h * 8));
                xhi[ks][h] = __ldcs(reinterpret_cast<const float2*>(xr1 + ks * 16 + h * 8));
            }
        }

        // ---- ||x||^2 for both rows (exact fp32), reduce over qq lanes ----
        float s0 = 0.f, s1 = 0.f;
        #pragma unroll
        for (int ks = 0; ks < 4; ks++) {
            #pragma unroll
            for (int h = 0; h < 2; h++) {
                s0 += xlo[ks][h].x * xlo[ks][h].x + xlo[ks][h].y * xlo[ks][h].y;
                s1 += xhi[ks][h].x * xhi[ks][h].x + xhi[ks][h].y * xhi[ks][h].y;
            }
        }
        s0 += __shfl_xor_sync(0xffffffffu, s0, 1);
        s0 += __shfl_xor_sync(0xffffffffu, s0, 2);
        s1 += __shfl_xor_sync(0xffffffffu, s1, 1);
        s1 += __shfl_xor_sync(0xffffffffu, s1, 2);
        const float xs = odd ? s1 : s0;          // the row this thread stores

        // ---- Pack A fragments (bf16) for all 4 k-steps ----
        uint32_t A[4][4];
        #pragma unroll
        for (int ks = 0; ks < 4; ks++) {
            A[ks][0] = pack_bf16(xlo[ks][0].x, xlo[ks][0].y);
            A[ks][1] = pack_bf16(xhi[ks][0].x, xhi[ks][0].y);
            A[ks][2] = pack_bf16(xlo[ks][1].x, xlo[ks][1].y);
            A[ks][3] = pack_bf16(xhi[ks][1].x, xhi[ks][1].y);
        }

        float* orow = out + (size_t)(row0 + gq + odd * 8) * UNITS + cq;

        // ---- 8 chunks of 64 columns; B streamed from SMEM ----
        #pragma unroll 1
        for (int c = 0; c < 8; c++) {
            const int n0 = c * 64;
            float acc[8][4];
            #pragma unroll
            for (int i = 0; i < 8; i++)
                #pragma unroll
                for (int j = 0; j < 4; j++) acc[i][j] = 0.f;

            #pragma unroll
            for (int ks = 0; ks < 4; ks++) {
                #pragma unroll
                for (int g = 0; g < 4; g++) {
                    uint32_t b0, b1, b2, b3;
                    ldsm_x4(b0, b1, b2, b3,
                            bb + (uint32_t)(n0 + g * 16) * ROW_BYTES + ks * 32);
                    mma_bf16(acc[2 * g + 0], A[ks][0], A[ks][1], A[ks][2], A[ks][3], b0, b2);
                    mma_bf16(acc[2 * g + 1], A[ks][0], A[ks][1], A[ks][2], A[ks][3], b1, b3);
                }
            }

            // ---- Epilogue: pair-exchange to float4 rows, out = xs + ws - 2*acc ----
            #pragma unroll
            for (int nb = 0; nb < 8; nb++) {
                const float t0 = odd ? acc[nb][0] : acc[nb][2];
                const float t1 = odd ? acc[nb][1] : acc[nb][3];
                const float r0 = __shfl_xor_sync(0xffffffffu, t0, 1);
                const float r1 = __shfl_xor_sync(0xffffffffu, t1, 1);
                float c0, c1, c2, c3;
                if (odd) { c0 = r0; c1 = r1; c2 = acc[nb][2]; c3 = acc[nb][3]; }
                else     { c0 = acc[nb][0]; c1 = acc[nb][1]; c2 = r0; c3 = r1; }
                // broadcast LDS: only 2 distinct addresses per warp
                const float4 ws = *reinterpret_cast<const float4*>(
                    smem + SM_WSQ + (n0 + nb * 8 + cq) * 4);
                float4 o;
                o.x = fmaf(-2.f, c0, xs + ws.x);
                o.y = fmaf(-2.f, c1, xs + ws.y);
                o.z = fmaf(-2.f, c2, xs + ws.z);
                o.w = fmaf(-2.f, c3, xs + ws.w);
                __stcs(reinterpret_cast<float4*>(orow + n0 + nb * 8), o);
            }
        }
    }
}

extern "C" void kernel_launch(void* const* d_in, const int* in_sizes, int n_in,
                              void* d_out, int out_size) {
    const float* x = (const float*)d_in[0];
    const float* w = (const float*)d_in[1];
    float* out = (float*)d_out;
    cudaFuncSetAttribute(l2dist_kernel, cudaFuncAttributeMaxDynamicSharedMemorySize, SMEM_TOTAL);
    l2dist_kernel<<<GRID_X, NTHREADS, SMEM_TOTAL>>>(x, w, out);
}

// round 6
// speedup vs baseline: 1.3272x; 1.3272x over previous
#include <cuda_runtime.h>
#include <cuda_bf16.h>
#include <cstdint>

// Problem constants (fixed by dataset)
#define BATCH   131072
#define UNITS   512
#define DIMK    64
#define M_TILE  128
#define N_TILES (BATCH / M_TILE)   // 1024
#define GRID_X  148
#define NTHREADS 256               // 8 warps; each warp owns a 64-col strip

// ---------------- SMEM layout ----------------
static constexpr int ROW_BYTES = 144;                     // bf16 rows padded (ldmatrix)
static constexpr int SM_WSQ  = 0;                         // 512 f32 -> 2048
static constexpr int SM_XSQ0 = 2048;                      // 128 f32 -> 2560
static constexpr int SM_XSQ1 = 2560;                      // 128 f32 -> 3072
static constexpr int SM_X0   = 3072;                      // 128*144 -> 21504
static constexpr int SM_X1   = 21504;                     // -> 39936
static constexpr int SM_WST  = 39936;                     // 512*144 -> 113664
static constexpr int SM_STG  = 113664;                    // 8 warps * 4KB -> 146432
static constexpr int SMEM_TOTAL = SM_STG + 8 * 4096;

static __device__ __forceinline__ uint32_t smem_u32(const void* p) {
    uint32_t a;
    asm("{ .reg .u64 t; cvta.to.shared.u64 t, %1; cvt.u32.u64 %0, t; }" : "=r"(a) : "l"(p));
    return a;
}

static __device__ __forceinline__ void ldsm_x4(uint32_t& r0, uint32_t& r1, uint32_t& r2,
                                               uint32_t& r3, uint32_t addr) {
    asm volatile("ldmatrix.sync.aligned.m8n8.x4.shared.b16 {%0,%1,%2,%3}, [%4];"
                 : "=r"(r0), "=r"(r1), "=r"(r2), "=r"(r3) : "r"(addr));
}

static __device__ __forceinline__ void mma_bf16(float c[4], uint32_t a0, uint32_t a1,
                                                uint32_t a2, uint32_t a3,
                                                uint32_t b0, uint32_t b1) {
    asm volatile(
        "mma.sync.aligned.m16n8k16.row.col.f32.bf16.bf16.f32 "
        "{%0,%1,%2,%3}, {%4,%5,%6,%7}, {%8,%9}, {%0,%1,%2,%3};"
        : "+f"(c[0]), "+f"(c[1]), "+f"(c[2]), "+f"(c[3])
        : "r"(a0), "r"(a1), "r"(a2), "r"(a3), "r"(b0), "r"(b1));
}

static __device__ __forceinline__ uint32_t pack_bf16(float a, float b) {
    __nv_bfloat162 t = __floats2bfloat162_rn(a, b);
    return *reinterpret_cast<uint32_t*>(&t);
}

__global__ void __launch_bounds__(NTHREADS, 1)
l2dist_kernel(const float* __restrict__ x, const float* __restrict__ w,
              float* __restrict__ out) {
    extern __shared__ char smem[];
    const uint32_t sb = smem_u32(smem);
    const int tid  = threadIdx.x;
    const int wid  = tid >> 5;
    const int lane = tid & 31;

    // ---- Stage W -> bf16 SMEM (padded rows) + exact fp32 ||w||^2 ----
    #pragma unroll
    for (int rr = 0; rr < 2; rr++) {
        const int u = rr * NTHREADS + tid;
        const float* wr = w + (size_t)u * DIMK;
        float sq = 0.f;
        #pragma unroll
        for (int g = 0; g < 8; g++) {
            float4 a = *reinterpret_cast<const float4*>(wr + 8 * g);
            float4 b = *reinterpret_cast<const float4*>(wr + 8 * g + 4);
            sq += a.x * a.x + a.y * a.y + a.z * a.z + a.w * a.w
                + b.x * b.x + b.y * b.y + b.z * b.z + b.w * b.w;
            uint4 pk;
            pk.x = pack_bf16(a.x, a.y); pk.y = pack_bf16(a.z, a.w);
            pk.z = pack_bf16(b.x, b.y); pk.w = pack_bf16(b.z, b.w);
            *reinterpret_cast<uint4*>(smem + SM_WST + u * ROW_BYTES + g * 16) = pk;
        }
        *reinterpret_cast<float*>(smem + SM_WSQ + u * 4) = sq;
    }
    __syncthreads();

    // ---- Load this warp's B fragments ONCE (64 cols x 64 k) : 64 regs ----
    const int n_w = wid * 64;
    uint32_t Bf[4][4][4];   // [n16-group][ks][frag]
    {
        const uint32_t bb = sb + SM_WST + (uint32_t)(lane & 15) * ROW_BYTES
                          + (uint32_t)((lane >> 4) * 16);
        #pragma unroll
        for (int g = 0; g < 4; g++)
            #pragma unroll
            for (int ks = 0; ks < 4; ks++)
                ldsm_x4(Bf[g][ks][0], Bf[g][ks][1], Bf[g][ks][2], Bf[g][ks][3],
                        bb + (uint32_t)(n_w + g * 16) * ROW_BYTES + ks * 32);
    }

    const int gq = lane >> 2;           // 0..7
    const int qq = lane & 3;            // 0..3

    // ws for the store-side column mapping: cols n_w + (lane&15)*4 .. +3
    const float4 ws4 = *reinterpret_cast<const float4*>(
        smem + SM_WSQ + (n_w + (lane & 15) * 4) * 4);

    const uint32_t a_lane_off = (uint32_t)(lane & 15) * ROW_BYTES
                              + (uint32_t)((lane >> 4) * 16);
    char* const stg = smem + SM_STG + wid * 4096;
    const int rd_row  = (lane >> 4);         // 0/1
    const int rd_colg = lane & 15;

    const int ld_r0 = tid >> 4;
    const int ld_k  = (tid & 15) * 4;

    int t = blockIdx.x;

    // ---- Preload first tile into buffer 0 ----
    if (t < N_TILES) {
        #pragma unroll
        for (int it = 0; it < 8; it++) {
            const int r = it * 16 + ld_r0;
            float4 v = __ldcs(reinterpret_cast<const float4*>(
                x + (size_t)(t * M_TILE + r) * DIMK + ld_k));
            float sq = v.x * v.x + v.y * v.y + v.z * v.z + v.w * v.w;
            sq += __shfl_xor_sync(0xffffffffu, sq, 1);
            sq += __shfl_xor_sync(0xffffffffu, sq, 2);
            sq += __shfl_xor_sync(0xffffffffu, sq, 4);
            sq += __shfl_xor_sync(0xffffffffu, sq, 8);
            uint2 pk; pk.x = pack_bf16(v.x, v.y); pk.y = pack_bf16(v.z, v.w);
            *reinterpret_cast<uint2*>(smem + SM_X0 + r * ROW_BYTES + ld_k * 2) = pk;
            if ((tid & 15) == 0)
                *reinterpret_cast<float*>(smem + SM_XSQ0 + r * 4) = sq;
        }
    }
    __syncthreads();

    int cur = 0;
    for (; t < N_TILES; t += GRID_X, cur ^= 1) {
        const int tn = t + GRID_X;
        const bool more = (tn < N_TILES);
        const uint32_t xb = cur ? SM_X1 : SM_X0;
        const uint32_t xq = cur ? SM_XSQ1 : SM_XSQ0;
        const int row0 = t * M_TILE;

        float4 pvA[4], pvB[4];
        if (more) {
            #pragma unroll
            for (int it = 0; it < 4; it++)
                pvA[it] = __ldcs(reinterpret_cast<const float4*>(
                    x + (size_t)(tn * M_TILE + it * 16 + ld_r0) * DIMK + ld_k));
        }

        #pragma unroll
        for (int rb = 0; rb < 8; rb++) {
            if (rb == 4 && more) {
                #pragma unroll
                for (int it = 0; it < 4; it++)
                    pvB[it] = __ldcs(reinterpret_cast<const float4*>(
                        x + (size_t)(tn * M_TILE + (it + 4) * 16 + ld_r0) * DIMK + ld_k));
            }

            const uint32_t abase = sb + xb + (uint32_t)(rb * 16) * ROW_BYTES + a_lane_off;
            float acc[8][4];
            #pragma unroll
            for (int i = 0; i < 8; i++)
                #pragma unroll
                for (int j = 0; j < 4; j++) acc[i][j] = 0.f;

            #pragma unroll
            for (int ks = 0; ks < 4; ks++) {
                uint32_t a0, a1, a2, a3;
                ldsm_x4(a0, a1, a2, a3, abase + ks * 32);
                #pragma unroll
                for (int g = 0; g < 4; g++) {
                    mma_bf16(acc[2 * g + 0], a0, a1, a2, a3, Bf[g][ks][0], Bf[g][ks][2]);
                    mma_bf16(acc[2 * g + 1], a0, a1, a2, a3, Bf[g][ks][1], Bf[g][ks][3]);
                }
            }

            // ---- Stage raw acc into warp-private swizzled buffer (STS.64) ----
            // 8B-granule index h = row*32 + nb*4 + qq, swizzled h ^= (gq<<2)
            #pragma unroll
            for (int nb = 0; nb < 8; nb++) {
                const uint32_t h  = (uint32_t)(gq * 32 + nb * 4 + qq) ^ ((uint32_t)gq << 2);
                const uint32_t hh = h + 8 * 32;   // row gq+8: same swizzle, +256 granules
                *reinterpret_cast<float2*>(stg + h * 8)
                    = make_float2(acc[nb][0], acc[nb][1]);
                *reinterpret_cast<float2*>(stg + hh * 8)
                    = make_float2(acc[nb][2], acc[nb][3]);
            }
            __syncwarp();

            // ---- Read back row-major, apply epilogue, full-line STG ----
            #pragma unroll
            for (int i = 0; i < 8; i++) {
                const int row = i * 2 + rd_row;
                const uint32_t g16 = (uint32_t)(row * 16 + rd_colg)
                                   ^ (((uint32_t)(row & 7)) << 1);
                const float4 v = *reinterpret_cast<const float4*>(stg + g16 * 16);
                const float xsv = *reinterpret_cast<const float*>(
                    smem + xq + (rb * 16 + row) * 4);
                float4 o;
                o.x = fmaf(-2.f, v.x, xsv + ws4.x);
                o.y = fmaf(-2.f, v.y, xsv + ws4.y);
                o.z = fmaf(-2.f, v.z, xsv + ws4.z);
                o.w = fmaf(-2.f, v.w, xsv + ws4.w);
                __stcs(reinterpret_cast<float4*>(
                    out + (size_t)(row0 + rb * 16 + row) * UNITS + n_w + rd_colg * 4), o);
            }
            __syncwarp();
        }

        // ---- Commit prefetched tile to the other buffer ----
        if (more) {
            const uint32_t xbn = cur ? SM_X0 : SM_X1;
            const uint32_t xqn = cur ? SM_XSQ0 : SM_XSQ1;
            #pragma unroll
            for (int it = 0; it < 8; it++) {
                const int r = it * 16 + ld_r0;
                float4 v = (it < 4) ? pvA[it] : pvB[it - 4];
                float sq = v.x * v.x + v.y * v.y + v.z * v.z + v.w * v.w;
                sq += __shfl_xor_sync(0xffffffffu, sq, 1);
                sq += __shfl_xor_sync(0xffffffffu, sq, 2);
                sq += __shfl_xor_sync(0xffffffffu, sq, 4);
                sq += __shfl_xor_sync(0xffffffffu, sq, 8);
                uint2 pk; pk.x = pack_bf16(v.x, v.y); pk.y = pack_bf16(v.z, v.w);
                *reinterpret_cast<uint2*>(smem + xbn + r * ROW_BYTES + ld_k * 2) = pk;
                if ((tid & 15) == 0)
                    *reinterpret_cast<float*>(smem + xqn + r * 4) = sq;
            }
        }
        __syncthreads();
    }
}

extern "C" void kernel_launch(void* const* d_in, const int* in_sizes, int n_in,
                              void* d_out, int out_size) {
    const float* x = (const float*)d_in[0];
    const float* w = (const float*)d_in[1];
    float* out = (float*)d_out;
    cudaFuncSetAttribute(l2dist_kernel, cudaFuncAttributeMaxDynamicSharedMemorySize, SMEM_TOTAL);
    l2dist_kernel<<<GRID_X, NTHREADS, SMEM_TOTAL>>>(x, w, out);
}